// round 12
// baseline (speedup 1.0000x reference)
#include <cuda_runtime.h>

#define B 128
#define K 17
#define HW 9216          // 96*96
#define NVEC (HW/4)      // 2304
#define TOPK 8
#define THREADS1 256
#define NBLOCKS (B * K)  // 2176

__device__ float g_per_joint[B * K];
__device__ unsigned int g_counter = 0;

__global__ void __launch_bounds__(THREADS1, 4)
mse_ohkm_warp0_kernel(const float* __restrict__ pred,
                      const float* __restrict__ gt,
                      const float* __restrict__ tw,
                      float* __restrict__ out) {
    const int bk   = blockIdx.x;
    const int tid  = threadIdx.x;
    const int lane = tid & 31;
    const int wid  = tid >> 5;

    const float4* __restrict__ p = reinterpret_cast<const float4*>(pred + (size_t)bk * HW);
    const float4* __restrict__ g = reinterpret_cast<const float4*>(gt   + (size_t)bk * HW);

    float acc = 0.0f;
    #pragma unroll
    for (int j = 0; j < NVEC / THREADS1; j++) {   // 9 iterations
        const int i = tid + j * THREADS1;
        float4 a = p[i];
        float4 b = g[i];
        float d0 = a.x - b.x;
        float d1 = a.y - b.y;
        float d2 = a.z - b.z;
        float d3 = a.w - b.w;
        acc += d0 * d0 + d1 * d1 + d2 * d2 + d3 * d3;
    }

    #pragma unroll
    for (int off = 16; off > 0; off >>= 1)
        acc += __shfl_down_sync(0xFFFFFFFFu, acc, off);

    __shared__ float warp_sums[THREADS1 / 32];
    if (lane == 0) warp_sums[wid] = acc;
    __syncthreads();

    if (wid != 0) return;            // 7 of 8 warps retire immediately

    // ---- warp 0 only: fold, store, count ----
    float v = (lane < THREADS1 / 32) ? warp_sums[lane] : 0.0f;
    #pragma unroll
    for (int off = 4; off > 0; off >>= 1)
        v += __shfl_down_sync(0xFFFFFFFFu, v, off);

    unsigned int old = 0u;
    if (lane == 0) {
        const float w = tw[bk];
        g_per_joint[bk] = v * w * w * (1.0f / (float)HW);
        // release-atomic orders the store above; no other warp waits on this
        asm volatile("atom.add.release.gpu.global.u32 %0, [%1], 1;"
                     : "=r"(old) : "l"(&g_counter) : "memory");
    }
    old = __shfl_sync(0xFFFFFFFFu, old, 0);
    if (old != (unsigned int)(NBLOCKS - 1)) return;

    // ---- globally last warp: OHKM top-8 for all B samples (L2-hot) ----
    asm volatile("fence.acq_rel.gpu;" ::: "memory");

    float total = 0.0f;
    #pragma unroll
    for (int q = 0; q < B / 32; q++) {          // 4 samples per lane
        const int b = lane + q * 32;
        const float* row = &g_per_joint[b * K];

        float t[TOPK];
        #pragma unroll
        for (int j = 0; j < TOPK; j++) t[j] = -3.4e38f;

        #pragma unroll
        for (int i = 0; i < K; i++) {
            float x = __ldcg(&row[i]);
            #pragma unroll
            for (int j = 0; j < TOPK; j++) {
                float o = t[j];
                bool gtp = x > o;
                t[j] = gtp ? x : o;
                x    = gtp ? o : x;
            }
        }
        #pragma unroll
        for (int j = 0; j < TOPK; j++) total += t[j];
    }

    #pragma unroll
    for (int off = 16; off > 0; off >>= 1)
        total += __shfl_down_sync(0xFFFFFFFFu, total, off);

    if (lane == 0) {
        out[0] = total * (1.0f / (float)(B * TOPK));
        g_counter = 0u;   // reset for next graph replay
    }
}

extern "C" void kernel_launch(void* const* d_in, const int* in_sizes, int n_in,
                              void* d_out, int out_size) {
    const float* pred = (const float*)d_in[0];   // output [B,K,H,W]
    const float* gt   = (const float*)d_in[1];   // target [B,K,H,W]
    const float* tw   = (const float*)d_in[2];   // target_weight [B,K,1]
    float* out = (float*)d_out;

    mse_ohkm_warp0_kernel<<<NBLOCKS, THREADS1>>>(pred, gt, tw, out);
}

// round 13
// speedup vs baseline: 1.1404x; 1.1404x over previous
#include <cuda_runtime.h>

#define B 128
#define K 17
#define HW 9216          // 96*96
#define NVEC (HW/4)      // 2304
#define TOPK 8
#define THREADS1 256
#define NPJ (B * K)      // 2176
#define T2 1024

__device__ float g_per_joint[B * K];

__global__ void __launch_bounds__(THREADS1, 4)
mse_per_joint_kernel(const float* __restrict__ pred,
                     const float* __restrict__ gt,
                     const float* __restrict__ tw) {
    const int bk = blockIdx.x;                    // 0 .. B*K-1
    const float4* __restrict__ p = reinterpret_cast<const float4*>(pred + (size_t)bk * HW);
    const float4* __restrict__ g = reinterpret_cast<const float4*>(gt   + (size_t)bk * HW);

    float acc = 0.0f;
    #pragma unroll
    for (int j = 0; j < NVEC / THREADS1; j++) {   // 9 iterations, fully unrolled
        const int i = threadIdx.x + j * THREADS1;
        float4 a = p[i];
        float4 b = g[i];
        float d0 = a.x - b.x;
        float d1 = a.y - b.y;
        float d2 = a.z - b.z;
        float d3 = a.w - b.w;
        acc += d0 * d0 + d1 * d1 + d2 * d2 + d3 * d3;
    }

    // warp reduce
    #pragma unroll
    for (int off = 16; off > 0; off >>= 1)
        acc += __shfl_down_sync(0xFFFFFFFFu, acc, off);

    __shared__ float warp_sums[THREADS1 / 32];
    const int lane = threadIdx.x & 31;
    const int wid  = threadIdx.x >> 5;
    if (lane == 0) warp_sums[wid] = acc;
    __syncthreads();

    if (wid == 0) {
        float v = (lane < THREADS1 / 32) ? warp_sums[lane] : 0.0f;
        #pragma unroll
        for (int off = 4; off > 0; off >>= 1)
            v += __shfl_down_sync(0xFFFFFFFFu, v, off);
        if (lane == 0) {
            const float w = tw[bk];
            g_per_joint[bk] = v * w * w * (1.0f / (float)HW);
        }
    }
}

__global__ void __launch_bounds__(T2, 1)
ohkm_topk_kernel(float* __restrict__ out) {
    const int tid  = threadIdx.x;
    const int lane = tid & 31;
    const int wid  = tid >> 5;

    __shared__ float pj[NPJ];        // all per-joint values, loaded in parallel
    __shared__ float wsum[4];

    // ---- phase 1: gang-load 2176 floats (fully parallel, one L2 trip) ----
    {
        float v0 = g_per_joint[tid];
        float v1 = g_per_joint[tid + T2];
        float v2 = (tid < NPJ - 2 * T2) ? g_per_joint[tid + 2 * T2] : 0.0f;
        pj[tid] = v0;
        pj[tid + T2] = v1;
        if (tid < NPJ - 2 * T2) pj[tid + 2 * T2] = v2;
    }
    __syncthreads();

    // ---- phase 2: threads 0..127 do top-8 from hot smem ----
    float s = 0.0f;
    if (tid < B) {
        float t[TOPK];
        #pragma unroll
        for (int j = 0; j < TOPK; j++) t[j] = -3.4e38f;

        #pragma unroll
        for (int i = 0; i < K; i++) {
            float x = pj[tid * K + i];
            #pragma unroll
            for (int j = 0; j < TOPK; j++) {
                float o = t[j];
                bool gtp = x > o;
                t[j] = gtp ? x : o;
                x    = gtp ? o : x;
            }
        }
        #pragma unroll
        for (int j = 0; j < TOPK; j++) s += t[j];
    }

    // ---- phase 3: shuffle reduce (warps 0..3 hold the 128 sums) ----
    if (wid < 4) {
        #pragma unroll
        for (int off = 16; off > 0; off >>= 1)
            s += __shfl_down_sync(0xFFFFFFFFu, s, off);
        if (lane == 0) wsum[wid] = s;
    }
    __syncthreads();
    if (tid == 0)
        out[0] = (wsum[0] + wsum[1] + wsum[2] + wsum[3])
                 * (1.0f / (float)(B * TOPK));
}

extern "C" void kernel_launch(void* const* d_in, const int* in_sizes, int n_in,
                              void* d_out, int out_size) {
    const float* pred = (const float*)d_in[0];   // output [B,K,H,W]
    const float* gt   = (const float*)d_in[1];   // target [B,K,H,W]
    const float* tw   = (const float*)d_in[2];   // target_weight [B,K,1]
    float* out = (float*)d_out;

    mse_per_joint_kernel<<<NPJ, THREADS1>>>(pred, gt, tw);
    ohkm_topk_kernel<<<1, T2>>>(out);
}